// round 8
// baseline (speedup 1.0000x reference)
#include <cuda_runtime.h>
#include <stdint.h>
#include <cooperative_groups.h>
namespace cg = cooperative_groups;

#define BATCH 16
#define WPR 16
#define WPI 8192
#define NPIX 4194304
#define NBLK 2048
#define ROWS_CTA 128
#define NGRP 32
#define SSTRIDE 18
#define SBUF (ROWS_CTA*SSTRIDE)
#define S1ROWS (ROWS_CTA+2)      // rows -1..128
#define PCB 128

// ---------------- scratch (no allocation allowed) ----------------
__device__ uint32_t g_pred[BATCH*WPI];
__device__ uint32_t g_true[BATCH*WPI];
__device__ uint32_t g_ps[BATCH*WPI];
__device__ uint32_t g_ts[BATCH*WPI];
__device__ float    g_part[4*NBLK];
__device__ int      g_icnt[BATCH];
__device__ int      g_pcnt[BATCH];
__device__ int      g_tcnt[BATCH];
__device__ int      g_ctr;

// ---------------- kernel A: binarize + dice/focal partials -------
__global__ __launch_bounds__(256, 7) void kA(const float* __restrict__ logits,
                                             const int*   __restrict__ tr){
    int tid = threadIdx.x;
    int gt  = blockIdx.x*256 + tid;
    int i8  = gt*8;
    int b   = i8 >> 18;
    int rem = i8 & ((1<<18)-1);

    const float4* F = (const float4*)logits;
    size_t q0 = (((size_t)(2*b) << 18) + rem) >> 2;
    size_t q1 = q0 + (1u << 16);
    const int4* T4 = (const int4*)tr;
    size_t qt = ((size_t)i8) >> 2;

    float4 A0 = F[q0], A1 = F[q0+1];
    float4 B0 = F[q1], B1 = F[q1+1];
    int4   t0 = T4[qt], t1 = T4[qt+1];

    float L0[8] = {A0.x,A0.y,A0.z,A0.w,A1.x,A1.y,A1.z,A1.w};
    float L1[8] = {B0.x,B0.y,B0.z,B0.w,B1.x,B1.y,B1.z,B1.w};
    int   TT[8] = {t0.x,t0.y,t0.z,t0.w,t1.x,t1.y,t1.z,t1.w};

    unsigned pm = 0, tm = 0;
    float s1 = 0.f, s2 = 0.f, s3 = 0.f, s4 = 0.f;
    #pragma unroll
    for (int j = 0; j < 8; j++){
        float d = L1[j] - L0[j];
        bool pd = d > 0.f;
        bool tp = TT[j] > 0;
        pm |= (unsigned)pd << j;
        tm |= (unsigned)tp << j;
        float ad = fabsf(d);
        float e  = __expf(-ad);
        float pb = __fdividef(1.f, 1.f + e);
        float lg = -__logf(pb);
        float p1 = pd ? pb : 1.f - pb;
        float ce = (tp == pd) ? lg : (ad + lg);
        float pt = tp ? p1 : 1.f - p1;
        float om = 1.f - pt;
        s4 += 0.25f * om * om * ce;
        s2 += p1;
        s1 += tp ? p1 : 0.f;
        s3 += tp ? 1.f : 0.f;
    }
    ((uint8_t*)g_pred)[gt] = (uint8_t)pm;
    ((uint8_t*)g_true)[gt] = (uint8_t)tm;

    __shared__ float red[8*4];
    int lane = tid & 31, wid = tid >> 5;
    float vals[4] = {s1, s2, s3, s4};
    #pragma unroll
    for (int v = 0; v < 4; v++){
        float x = vals[v];
        #pragma unroll
        for (int o = 16; o; o >>= 1) x += __shfl_down_sync(0xffffffffu, x, o);
        if (lane == 0) red[wid*4 + v] = x;
    }
    __syncthreads();
    if (wid == 0 && lane < 4){
        float s = 0.f;
        #pragma unroll
        for (int w = 0; w < 8; w++) s += red[w*4 + lane];
        g_part[lane*NBLK + blockIdx.x] = s;
    }
}

// ---------------- Zhang-Suen core (bit-parallel, 32 px/word) -----
template<int SUB>
__device__ __forceinline__ uint32_t zs_core(uint32_t cC,
    uint32_t p2,uint32_t p3,uint32_t p4,uint32_t p5,
    uint32_t p6,uint32_t p7,uint32_t p8,uint32_t p9)
{
    uint32_t sa = p2 ^ p3 ^ p4, ca = (p2 & p3) | (p4 & (p2 ^ p3));
    uint32_t sb = p5 ^ p6 ^ p7, cb = (p5 & p6) | (p7 & (p5 ^ p6));
    uint32_t sc = p8 ^ p9,      cc = p8 & p9;
    uint32_t S0v = sa ^ sb ^ sc, cd = (sa & sb) | (sc & (sa ^ sb));
    uint32_t t1v = ca ^ cb ^ cc, c1a = (ca & cb) | (cc & (ca ^ cb));
    uint32_t S1v = t1v ^ cd,     c1b = t1v & cd;
    uint32_t S2v = c1a ^ c1b,    S3v = c1a & c1b;
    uint32_t cond1 = (S1v | S2v | S3v) & ~(S3v | (S2v & S1v & S0v));

    uint32_t t0 = ~p2 & p3, t1 = ~p3 & p4, t2 = ~p4 & p5, t3 = ~p5 & p6;
    uint32_t t4 = ~p6 & p7, t5 = ~p7 & p8, t6 = ~p8 & p9, t7 = ~p9 & p2;
    uint32_t onep = t0, two = 0;
    two |= onep & t1; onep |= t1;
    two |= onep & t2; onep |= t2;
    two |= onep & t3; onep |= t3;
    two |= onep & t4; onep |= t4;
    two |= onep & t5; onep |= t5;
    two |= onep & t6; onep |= t6;
    two |= onep & t7; onep |= t7;
    uint32_t condA = onep & ~two;

    uint32_t c3m, c4m;
    if (SUB == 0){ c3m = ~(p2 & p4 & p6); c4m = ~(p4 & p6 & p8); }
    else         { c3m = ~(p2 & p4 & p8); c4m = ~(p2 & p6 & p8); }
    return cC & cond1 & condA & c3m & c4m;   // removal mask
}

#define LDROW(ptr, c, l, r) do{ const uint32_t* _p=(ptr); \
    c=_p[w]; l=(w>0)?_p[w-1]:0u; r=(w<15)?_p[w+1]:0u; }while(0)

// single-row Zhang-Suen for halo rows
template<int SUB>
__device__ __forceinline__ uint32_t zs_row(
    uint32_t cN,uint32_t lN,uint32_t rN,
    uint32_t cC,uint32_t lC,uint32_t rC,
    uint32_t cS,uint32_t lS,uint32_t rS, uint32_t& outNew)
{
    uint32_t p2=cN, p6=cS;
    uint32_t p3=__funnelshift_r(cN,rN,1), p9=__funnelshift_l(lN,cN,1);
    uint32_t p4=__funnelshift_r(cC,rC,1), p8=__funnelshift_l(lC,cC,1);
    uint32_t p5=__funnelshift_r(cS,rS,1), p7=__funnelshift_l(lS,cS,1);
    uint32_t remv = zs_core<SUB>(cC,p2,p3,p4,p5,p6,p7,p8,p9);
    outNew = cC & ~remv;
    return remv;
}

// ---------------- kernel B: one cluster.sync per iteration -------
__global__ void __cluster_dims__(4,1,1) __launch_bounds__(512) kB(){
    __shared__ uint32_t S0[2][SBUF];            // ping-pong (sub1 dst alternates)
    __shared__ uint32_t S1h[S1ROWS*SSTRIDE];    // sub0 dst incl. halo rows -1,128
    __shared__ uint32_t act0[2][NGRP], act1[2][NGRP];  // [parity][group]
    __shared__ uint32_t mb_up[4], mb_dn[4];
    __shared__ uint32_t hact_up[2], hact_dn[2];
    __shared__ int s_flag[2];
    __shared__ int s_any;

    cg::cluster_group cl = cg::this_cluster();
    unsigned rank = cl.block_rank();
    int unit = blockIdx.x >> 2;
    int img  = unit >> 1;
    int sel  = unit & 1;
    const uint32_t* srcg = (sel ? g_true : g_pred) + img*WPI + rank*2048;
    uint32_t*       dstg = (sel ? g_ts   : g_ps)   + img*WPI + rank*2048;

    int tid = threadIdx.x;
    int g = tid >> 4, w = tid & 15;
    bool hasUp = rank > 0, hasDn = rank < 3;

    #pragma unroll
    for (int it = 0; it < 4; it++){
        int idx = tid + it*512;
        S0[0][(idx>>4)*SSTRIDE + (idx&15)] = srcg[idx];
    }
    if (tid < NGRP){
        act0[0][tid]=0xFFFFu; act0[1][tid]=0xFFFFu;
        act1[0][tid]=0xFFFFu; act1[1][tid]=0xFFFFu;
    }
    if (tid == 0){
        uint32_t u = hasUp ? 0xFFFFu : 0u;
        uint32_t d = hasDn ? 0xFFFFu : 0u;
        mb_up[0]=mb_up[1]=mb_up[2]=mb_up[3]=u;
        mb_dn[0]=mb_dn[1]=mb_dn[2]=mb_dn[3]=d;
        hact_up[0]=hact_up[1]=u;
        hact_dn[0]=hact_dn[1]=d;
        s_flag[0] = 1; s_flag[1] = 1;
    }
    if (!hasUp && tid < SSTRIDE) S1h[tid] = 0u;
    if (!hasDn && tid < SSTRIDE) S1h[(S1ROWS-1)*SSTRIDE + tid] = 0u;

    uint32_t* upS0b[2]; uint32_t* dnS0b[2];
    upS0b[0] = hasUp ? cl.map_shared_rank(&S0[0][0], rank-1) : (uint32_t*)0;
    upS0b[1] = hasUp ? cl.map_shared_rank(&S0[1][0], rank-1) : (uint32_t*)0;
    dnS0b[0] = hasDn ? cl.map_shared_rank(&S0[0][0], rank+1) : (uint32_t*)0;
    dnS0b[1] = hasDn ? cl.map_shared_rank(&S0[1][0], rank+1) : (uint32_t*)0;
    uint32_t* up_mbdn = hasUp ? cl.map_shared_rank(&mb_dn[0], rank-1) : (uint32_t*)0;
    uint32_t* dn_mbup = hasDn ? cl.map_shared_rank(&mb_up[0], rank+1) : (uint32_t*)0;
    int* fp0 = cl.map_shared_rank(&s_flag[0], 0);
    int* fp1 = cl.map_shared_rank(&s_flag[0], 1);
    int* fp2 = cl.map_shared_rank(&s_flag[0], 2);
    int* fp3 = cl.map_shared_rank(&s_flag[0], 3);

    cl.sync();   // inputs + mbarriers/flags visible cluster-wide

    uint32_t wm = (w == 0) ? 0x3u : (7u << (w - 1));
    int lane = tid & 31;
    int mbw = 0;
    int p = 0;
    for (;;){
        if (tid == 0){
            int q = p ^ 1;
            s_any = fp0[q] | fp1[q] | fp2[q] | fp3[q];
            s_flag[p] = 0;
        }
        __syncthreads();
        if (!s_any) break;

        const uint32_t* Scur = &S0[p][0];
        uint32_t*       Snxt = &S0[p^1][0];
        const uint32_t* uS = upS0b[p];
        const uint32_t* dS = dnS0b[p];

        // ======== SUBITER 0: Scur(+peer) -> S1h (rows -1..128) ========
        uint32_t actv0;
        {
            uint32_t am1 = (g == 0)      ? (mb_up[0]|mb_up[1]|mb_up[2]|mb_up[3])
                                         : (act0[p^1][g-1] | act1[p^1][g-1]);
            uint32_t a0  = act0[p^1][g] | act1[p^1][g];
            uint32_t ap1 = (g == NGRP-1) ? (mb_dn[0]|mb_dn[1]|mb_dn[2]|mb_dn[3])
                                         : (act0[p^1][g+1] | act1[p^1][g+1]);
            actv0 = (am1 | a0 | ap1) & wm;
        }
        bool ch0 = false;
        if (actv0){
            uint32_t C[6], E[6], Wt[6];
            #pragma unroll
            for (int i = 0; i < 6; i++){
                int r = 4*g - 1 + i;
                uint32_t c, l, rr;
                if (r >= 0 && r < ROWS_CTA){ LDROW(Scur + r*SSTRIDE, c, l, rr); }
                else if (r < 0){ if (uS){ LDROW(uS + 127*SSTRIDE, c, l, rr); } else { c=l=rr=0u; } }
                else           { if (dS){ LDROW(dS, c, l, rr); }              else { c=l=rr=0u; } }
                C[i]=c; E[i]=__funnelshift_r(c,rr,1); Wt[i]=__funnelshift_l(l,c,1);
            }
            #pragma unroll
            for (int k = 0; k < 4; k++){
                int i = k + 1;
                uint32_t remv = zs_core<0>(C[i], C[i-1],E[i-1],E[i],E[i+1],C[i+1],Wt[i+1],Wt[i],Wt[i-1]);
                S1h[(4*g + k + 1)*SSTRIDE + w] = C[i] & ~remv;
                ch0 = ch0 || (remv != 0u);
            }
            if (ch0) s_flag[p] = 1;
        }
        // halo rows (unconditional, local compute from peer data)
        bool hch = false;
        if (g == 0 && uS){
            uint32_t cN,lN,rN,cC,lC,rC,cS,lS,rS, nv;
            LDROW(uS + 126*SSTRIDE, cN,lN,rN);
            LDROW(uS + 127*SSTRIDE, cC,lC,rC);
            LDROW(Scur,             cS,lS,rS);
            uint32_t remv = zs_row<0>(cN,lN,rN, cC,lC,rC, cS,lS,rS, nv);
            S1h[0*SSTRIDE + w] = nv;                  // row -1
            hch = (remv != 0u);
        }
        if (g == NGRP-1 && dS){
            uint32_t cN,lN,rN,cC,lC,rC,cS,lS,rS, nv;
            LDROW(Scur + 127*SSTRIDE, cN,lN,rN);
            LDROW(dS,                 cC,lC,rC);
            LDROW(dS + SSTRIDE,       cS,lS,rS);
            uint32_t remv = zs_row<0>(cN,lN,rN, cC,lC,rC, cS,lS,rS, nv);
            S1h[(S1ROWS-1)*SSTRIDE + w] = nv;         // row 128
            hch = (remv != 0u);
        }
        // publish activity
        {
            unsigned bal = __ballot_sync(0xffffffffu, ch0);
            if (lane == 0 || lane == 16){
                uint32_t v = (lane == 0) ? (bal & 0xFFFFu) : (bal >> 16);
                act0[p][g] = v;
                if (g == 0       && up_mbdn) up_mbdn[mbw] = v;
                if (g == NGRP-1  && dn_mbup) dn_mbup[mbw] = v;
            }
            unsigned hbal = __ballot_sync(0xffffffffu, hch);
            if (tid == 0)   hact_up[p] = hasUp ? (hbal & 0xFFFFu) : 0u;
            if (tid == 511) hact_dn[p] = hasDn ? (hbal >> 16)     : 0u;
        }
        mbw = (mbw + 1) & 3;
        __syncthreads();   // S1h + act0 + hact complete

        // ======== SUBITER 1: S1h (local only) -> Snxt ========
        uint32_t actv1;
        {
            uint32_t mu4 = mb_up[0]|mb_up[1]|mb_up[2]|mb_up[3];
            uint32_t md4 = mb_dn[0]|mb_dn[1]|mb_dn[2]|mb_dn[3];
            uint32_t am1 = (g == 0)      ? (hact_up[0] | hact_up[1] | mu4)
                : (act0[0][g-1]|act0[1][g-1]|act1[0][g-1]|act1[1][g-1]);
            uint32_t a0  =  act0[0][g]  |act0[1][g]  |act1[0][g]  |act1[1][g];
            uint32_t ap1 = (g == NGRP-1) ? (hact_dn[0] | hact_dn[1] | md4)
                : (act0[0][g+1]|act0[1][g+1]|act1[0][g+1]|act1[1][g+1]);
            actv1 = (am1 | a0 | ap1) & wm;
        }
        __syncthreads();   // gate reads done before act1 overwrite
        bool ch1 = false;
        if (actv1){
            uint32_t C[6], E[6], Wt[6];
            #pragma unroll
            for (int i = 0; i < 6; i++){
                int r = 4*g - 1 + i;                 // -1..128, all local
                const uint32_t* rp = S1h + (r + 1)*SSTRIDE;
                uint32_t c = rp[w], l = (w>0)?rp[w-1]:0u, rr = (w<15)?rp[w+1]:0u;
                C[i]=c; E[i]=__funnelshift_r(c,rr,1); Wt[i]=__funnelshift_l(l,c,1);
            }
            #pragma unroll
            for (int k = 0; k < 4; k++){
                int i = k + 1;
                uint32_t remv = zs_core<1>(C[i], C[i-1],E[i-1],E[i],E[i+1],C[i+1],Wt[i+1],Wt[i],Wt[i-1]);
                Snxt[(4*g + k)*SSTRIDE + w] = C[i] & ~remv;
                ch1 = ch1 || (remv != 0u);
            }
            if (ch1) s_flag[p] = 1;
        }
        {
            unsigned bal = __ballot_sync(0xffffffffu, ch1);
            if (lane == 0 || lane == 16){
                uint32_t v = (lane == 0) ? (bal & 0xFFFFu) : (bal >> 16);
                act1[p][g] = v;
                if (g == 0       && up_mbdn) up_mbdn[mbw] = v;
                if (g == NGRP-1  && dn_mbup) dn_mbup[mbw] = v;
            }
        }
        mbw = (mbw + 1) & 3;
        cl.sync();         // single cluster sync per iteration
        p ^= 1;
    }

    #pragma unroll
    for (int it = 0; it < 4; it++){
        int idx = tid + it*512;
        dstg[idx] = S0[p][(idx>>4)*SSTRIDE + (idx&15)];
    }
}

// ---------------- kernel CD: parallel popcounts + final combine --
__global__ __launch_bounds__(256) void kCD(float* __restrict__ out){
    int tid = threadIdx.x;
    if (blockIdx.x < PCB){
        int b     = blockIdx.x >> 3;
        int slice = blockIdx.x & 7;
        const uint4* A  = (const uint4*)(g_ps + b*WPI + slice*1024);
        const uint4* Cc = (const uint4*)(g_ts + b*WPI + slice*1024);
        uint4 a = A[tid], c = Cc[tid];
        int inter = __popc(a.x & c.x) + __popc(a.y & c.y) + __popc(a.z & c.z) + __popc(a.w & c.w);
        int sp    = __popc(a.x) + __popc(a.y) + __popc(a.z) + __popc(a.w);
        int st    = __popc(c.x) + __popc(c.y) + __popc(c.z) + __popc(c.w);

        __shared__ int red[8*3];
        int lane = tid & 31, wid = tid >> 5;
        int v3[3] = {inter, sp, st};
        #pragma unroll
        for (int v = 0; v < 3; v++){
            int x = v3[v];
            #pragma unroll
            for (int o = 16; o; o >>= 1) x += __shfl_down_sync(0xffffffffu, x, o);
            if (lane == 0) red[wid*3 + v] = x;
        }
        __syncthreads();
        if (tid == 0){
            int ti = 0, tp = 0, tt = 0;
            #pragma unroll
            for (int w = 0; w < 8; w++){ ti += red[w*3]; tp += red[w*3+1]; tt += red[w*3+2]; }
            atomicAdd(&g_icnt[b], ti);
            atomicAdd(&g_pcnt[b], tp);
            atomicAdd(&g_tcnt[b], tt);
            __threadfence();
            atomicAdd(&g_ctr, 1);
        }
    } else {
        __shared__ float red[8*4];
        int lane = tid & 31, wid = tid >> 5;
        #pragma unroll
        for (int v = 0; v < 4; v++){
            const float4* P = (const float4*)(g_part + v*NBLK);
            float4 a = P[tid], b = P[tid + 256];
            float x = ((a.x + a.y) + (a.z + a.w)) + ((b.x + b.y) + (b.z + b.w));
            #pragma unroll
            for (int o = 16; o; o >>= 1) x += __shfl_down_sync(0xffffffffu, x, o);
            if (lane == 0) red[wid*4 + v] = x;
        }
        __syncthreads();
        if (tid == 0){
            float tot[4];
            #pragma unroll
            for (int v = 0; v < 4; v++){
                float s = 0.f;
                #pragma unroll
                for (int w = 0; w < 8; w++) s += red[w*4 + v];
                tot[v] = s;
            }
            while (atomicAdd(&g_ctr, 0) < PCB) { }
            __threadfence();
            float cls = 0.f;
            #pragma unroll
            for (int b = 0; b < BATCH; b++){
                float ti = (float)((volatile int*)g_icnt)[b];
                float dn = (float)(((volatile int*)g_pcnt)[b] + ((volatile int*)g_tcnt)[b]);
                cls += (2.f*ti + 1e-6f) / (dn + 1e-6f);
            }

            const float EPS = 1e-6f;
            float TOT = (float)NPIX;
            float s1 = tot[0], s2 = tot[1], n1 = tot[2], sf = tot[3];
            float s_i0 = (TOT - n1) - s2 + s1;
            float card0 = (TOT - s2) + (TOT - n1);
            float card1 = s2 + n1;
            float dice = 1.f - 0.5f * ((2.f*s_i0 + EPS)/(card0 + EPS)
                                     + (2.f*s1 + EPS)/(card1 + EPS));
            float cl = 1.f - cls / (float)BATCH;
            float focal = sf / TOT;
            out[0] = 0.7f*cl + 0.1f*dice + 0.2f*focal;

            #pragma unroll
            for (int b = 0; b < BATCH; b++){
                g_icnt[b] = 0; g_pcnt[b] = 0; g_tcnt[b] = 0;
            }
            __threadfence();
            atomicExch(&g_ctr, 0);
        }
    }
}

// ---------------- launch -----------------------------------------
extern "C" void kernel_launch(void* const* d_in, const int* in_sizes, int n_in,
                              void* d_out, int out_size){
    const float* logits = (const float*)d_in[0];
    const int*   tr     = (const int*)d_in[1];
    kA<<<NBLK, 256>>>(logits, tr);
    kB<<<8*BATCH, 512>>>();
    kCD<<<PCB+1, 256>>>((float*)d_out);
}